// round 1
// baseline (speedup 1.0000x reference)
#include <cuda_runtime.h>
#include <cuda_bf16.h>
#include <cstdint>

#define N_NODES 100000
#define N_EDGES 1600000
#define F_HID   64

// ---------------- scratch (device globals; no allocations) ----------------
__device__ float g_sum[(size_t)N_NODES * 64];   // aggregation accumulator (reused by both layers)
__device__ float g_deg[N_NODES];                // in-degree (float), computed once
__device__ float g_h[(size_t)N_NODES * 64];     // layer-1 output (relu)
__device__ int   g_is64;                        // edge_index element width flag

// ---------------- dtype width detection for edge_index ----------------
// int64 values in [0,100000) have all-zero high 32-bit words.
// For an int32 array, the first 256 words are random values in [0,100000):
// probability all 128 odd-position words are zero is ~0.
__global__ void detect_kernel(const int* __restrict__ ei32) {
    int odd_nonzero = 0;
    #pragma unroll 8
    for (int i = 0; i < 256; i += 2) {
        if (ei32[i + 1] != 0) odd_nonzero = 1;
    }
    g_is64 = odd_nonzero ? 0 : 1;
}

// ---------------- zero kernels ----------------
__global__ void zero_sum_deg_kernel() {
    int i = blockIdx.x * blockDim.x + threadIdx.x;
    const int n_sum4 = (N_NODES * 64) / 4;       // 1,600,000
    const int n_deg4 = N_NODES / 4;              // 25,000
    if (i < n_sum4) {
        ((float4*)g_sum)[i] = make_float4(0.f, 0.f, 0.f, 0.f);
    } else if (i < n_sum4 + n_deg4) {
        ((float4*)g_deg)[i - n_sum4] = make_float4(0.f, 0.f, 0.f, 0.f);
    }
}

__global__ void zero_sum_kernel() {
    int i = blockIdx.x * blockDim.x + threadIdx.x;
    if (i < (N_NODES * 64) / 4) {
        ((float4*)g_sum)[i] = make_float4(0.f, 0.f, 0.f, 0.f);
    }
}

// ---------------- edge scatter (segment-sum via vector reduction) ----------------
// thread t -> edge e = t/16, chunk c = t%16 (each chunk = 4 consecutive floats).
// feat row gather is coalesced (16 threads cover the 256B row);
// red.global.add.v4.f32 does a fire-and-forget 16B atomic add.
__global__ void scatter_kernel(const float* __restrict__ feat_ext,
                               const void*  __restrict__ ei,
                               int use_h, int do_deg) {
    long long tid = (long long)blockIdx.x * blockDim.x + threadIdx.x;
    if (tid >= (long long)N_EDGES * 16) return;
    int e = (int)(tid >> 4);
    int c = (int)(tid & 15);

    int src, dst;
    if (g_is64) {
        const long long* p = (const long long*)ei;
        src = (int)p[e];
        dst = (int)p[N_EDGES + e];
    } else {
        const int* p = (const int*)ei;
        src = p[e];
        dst = p[N_EDGES + e];
    }

    const float* feat = use_h ? g_h : feat_ext;
    float4 v = ((const float4*)(feat + (size_t)src * 64))[c];
    float* pdst = g_sum + (size_t)dst * 64 + c * 4;
    asm volatile("red.global.add.v4.f32 [%0], {%1,%2,%3,%4};"
                 :: "l"(pdst), "f"(v.x), "f"(v.y), "f"(v.z), "f"(v.w)
                 : "memory");

    if (do_deg && c == 0) {
        atomicAdd(&g_deg[dst], 1.0f);
    }
}

// ---------------- fused mean + dual-GEMM (+bias, optional relu) ----------------
// out[n][j] = relu?( sum_k mean[n][k]*Wn[k][j] + feat[n][k]*Ws[k][j] + b[j] )
// Weights transposed into smem ([j][k], pitch 68 floats -> LDS.128 conflict-free).
// 256 threads; G = 256/OUT nodes per group; grid-stride over node groups.
template<int OUT>
__global__ void sage_gemm_kernel(const float* __restrict__ feat_ext,
                                 const float* __restrict__ Wn,   // [64, OUT]
                                 const float* __restrict__ Ws,   // [64, OUT]
                                 const float* __restrict__ bias, // [OUT]
                                 float* __restrict__ out_ext,    // [N, OUT]
                                 int feat_is_h, int out_is_h, int relu) {
    constexpr int G = 256 / OUT;
    __shared__ float sWn[OUT][68];
    __shared__ float sWs[OUT][68];
    __shared__ float sb[OUT];
    __shared__ float sx[G][64];
    __shared__ float sm[G][64];

    const float* feat = feat_is_h ? g_h : feat_ext;
    float* out = out_is_h ? g_h : out_ext;

    int tid = threadIdx.x;
    for (int i = tid; i < 64 * OUT; i += 256) {
        int k = i / OUT, j = i % OUT;
        sWn[j][k] = Wn[i];
        sWs[j][k] = Ws[i];
    }
    if (tid < OUT) sb[tid] = bias[tid];
    __syncthreads();

    int j  = tid % OUT;
    int ln = tid / OUT;

    for (int base = blockIdx.x * G; base < N_NODES; base += gridDim.x * G) {
        __syncthreads();   // previous-iteration consumers done before overwrite
        // cooperative load of G node rows (feat + mean)
        for (int i = tid; i < G * 64; i += 256) {
            int lnode = i >> 6, k = i & 63;
            int n = base + lnode;
            if (n < N_NODES) {
                float inv = 1.0f / fmaxf(g_deg[n], 1.0f);
                sx[lnode][k] = feat[(size_t)n * 64 + k];
                sm[lnode][k] = g_sum[(size_t)n * 64 + k] * inv;
            }
        }
        __syncthreads();

        int n = base + ln;
        if (n < N_NODES) {
            float acc = sb[j];
            #pragma unroll
            for (int k4 = 0; k4 < 16; k4++) {
                float4 wn = *(const float4*)&sWn[j][k4 * 4];
                float4 ws = *(const float4*)&sWs[j][k4 * 4];
                float4 mv = *(const float4*)&sm[ln][k4 * 4];
                float4 xv = *(const float4*)&sx[ln][k4 * 4];
                acc = fmaf(mv.x, wn.x, acc);
                acc = fmaf(mv.y, wn.y, acc);
                acc = fmaf(mv.z, wn.z, acc);
                acc = fmaf(mv.w, wn.w, acc);
                acc = fmaf(xv.x, ws.x, acc);
                acc = fmaf(xv.y, ws.y, acc);
                acc = fmaf(xv.z, ws.z, acc);
                acc = fmaf(xv.w, ws.w, acc);
            }
            if (relu) acc = fmaxf(acc, 0.0f);
            out[(size_t)n * OUT + j] = acc;
        }
    }
}

// ---------------- launch ----------------
extern "C" void kernel_launch(void* const* d_in, const int* in_sizes, int n_in,
                              void* d_out, int out_size) {
    const float* x   = (const float*)d_in[0];
    const void*  ei  = d_in[1];
    const float* W1n = (const float*)d_in[2];
    const float* W1s = (const float*)d_in[3];
    const float* b1  = (const float*)d_in[4];
    const float* W2n = (const float*)d_in[5];
    const float* W2s = (const float*)d_in[6];
    const float* b2  = (const float*)d_in[7];
    float* out = (float*)d_out;

    // 0) detect edge_index element width
    detect_kernel<<<1, 1>>>((const int*)ei);

    // 1) zero accumulator + degree
    {
        int n4 = (N_NODES * 64) / 4 + N_NODES / 4;
        zero_sum_deg_kernel<<<(n4 + 255) / 256, 256>>>();
    }

    // 2) layer-1 scatter: sum x[src] into g_sum, count degree
    {
        long long total = (long long)N_EDGES * 16;
        int blocks = (int)((total + 255) / 256);
        scatter_kernel<<<blocks, 256>>>(x, ei, /*use_h=*/0, /*do_deg=*/1);
    }

    // 3) layer-1 transform: g_h = relu(mean@W1n + x@W1s + b1)
    sage_gemm_kernel<64><<<1184, 256>>>(x, W1n, W1s, b1, nullptr,
                                        /*feat_is_h=*/0, /*out_is_h=*/1, /*relu=*/1);

    // 4) re-zero accumulator
    {
        int n4 = (N_NODES * 64) / 4;
        zero_sum_kernel<<<(n4 + 255) / 256, 256>>>();
    }

    // 5) layer-2 scatter: sum g_h[src] into g_sum
    {
        long long total = (long long)N_EDGES * 16;
        int blocks = (int)((total + 255) / 256);
        scatter_kernel<<<blocks, 256>>>(nullptr, ei, /*use_h=*/1, /*do_deg=*/0);
    }

    // 6) layer-2 transform: out = mean2@W2n + g_h@W2s + b2
    sage_gemm_kernel<32><<<1184, 256>>>(nullptr, W2n, W2s, b2, out,
                                        /*feat_is_h=*/1, /*out_is_h=*/0, /*relu=*/0);
}

// round 2
// speedup vs baseline: 1.0501x; 1.0501x over previous
#include <cuda_runtime.h>
#include <cuda_bf16.h>
#include <cstdint>

#define N_NODES 100000
#define N_EDGES 1600000

// ---------------- scratch (device globals; no allocations) ----------------
__device__ float g_sum[(size_t)N_NODES * 64];   // aggregation accumulator (reused by both layers)
__device__ float g_deg[N_NODES];                // in-degree (float), computed once
__device__ float g_h[(size_t)N_NODES * 64];     // layer-1 output (relu)
__device__ int   g_is64;                        // edge_index element width flag

// ---------------- dtype width detection for edge_index ----------------
__global__ void detect_kernel(const int* __restrict__ ei32) {
    int odd_nonzero = 0;
    #pragma unroll 8
    for (int i = 0; i < 256; i += 2) {
        if (ei32[i + 1] != 0) odd_nonzero = 1;
    }
    g_is64 = odd_nonzero ? 0 : 1;
}

// ---------------- zero kernels ----------------
__global__ void zero_sum_deg_kernel() {
    int i = blockIdx.x * blockDim.x + threadIdx.x;
    const int n_sum4 = (N_NODES * 64) / 4;
    const int n_deg4 = N_NODES / 4;
    if (i < n_sum4) {
        ((float4*)g_sum)[i] = make_float4(0.f, 0.f, 0.f, 0.f);
    } else if (i < n_sum4 + n_deg4) {
        ((float4*)g_deg)[i - n_sum4] = make_float4(0.f, 0.f, 0.f, 0.f);
    }
}

__global__ void zero_sum_kernel() {
    int i = blockIdx.x * blockDim.x + threadIdx.x;
    if (i < (N_NODES * 64) / 4) {
        ((float4*)g_sum)[i] = make_float4(0.f, 0.f, 0.f, 0.f);
    }
}

// ---------------- edge scatter (segment-sum via vector reduction) ----------------
__global__ void scatter_kernel(const float* __restrict__ feat_ext,
                               const void*  __restrict__ ei,
                               int use_h, int do_deg) {
    long long tid = (long long)blockIdx.x * blockDim.x + threadIdx.x;
    if (tid >= (long long)N_EDGES * 16) return;
    int e = (int)(tid >> 4);
    int c = (int)(tid & 15);

    int src, dst;
    if (g_is64) {
        const long long* p = (const long long*)ei;
        src = (int)p[e];
        dst = (int)p[N_EDGES + e];
    } else {
        const int* p = (const int*)ei;
        src = p[e];
        dst = p[N_EDGES + e];
    }

    const float* feat = use_h ? g_h : feat_ext;
    float4 v = ((const float4*)(feat + (size_t)src * 64))[c];
    float* pdst = g_sum + (size_t)dst * 64 + c * 4;
    asm volatile("red.global.add.v4.f32 [%0], {%1,%2,%3,%4};"
                 :: "l"(pdst), "f"(v.x), "f"(v.y), "f"(v.z), "f"(v.w)
                 : "memory");

    if (do_deg && c == 0) {
        atomicAdd(&g_deg[dst], 1.0f);
    }
}

// ---------------- packed-f32x2 fused dual GEMM ----------------
// out[n][j] = relu?( sum_{k<64} mean[n][k]*Wn[k][j] + sum_{k<64} feat[n][k]*Ws[k][j] + b[j] )
// Block: 256 threads, 64 nodes. Thread layout: ln = tid>>2 (node), q = tid&3.
// Thread computes outputs j = j8*16 + q*4 + {0..3}, j8 = 0..OUT/16-1.
// Weights staged in smem [128][OUT] (k-major), read as broadcast LDS.128 ->
// ulonglong2 (pre-paired for fma.rn.f32x2). Node features read scalar from
// global (L1-resident: 8 rows/warp reused across 64 k iterations).
#define FMA2(acc, a2, b2) \
    asm("fma.rn.f32x2 %0, %1, %2, %0;" : "+l"(acc) : "l"(a2), "l"(b2))

template<int OUT>
__global__ __launch_bounds__(256)
void sage_gemm2_kernel(const float* __restrict__ feat_ext,
                       const float* __restrict__ Wn,   // [64, OUT]
                       const float* __restrict__ Ws,   // [64, OUT]
                       const float* __restrict__ bias, // [OUT]
                       float* __restrict__ out_ext,    // [N, OUT]
                       int feat_is_h, int out_is_h, int relu) {
    constexpr int NODES = 64;
    constexpr int JB = OUT / 16;           // j8 blocks per thread (4 or 2)
    __shared__ float sW[128 * OUT];
    __shared__ float sb[OUT];

    const float* feat = feat_is_h ? g_h : feat_ext;
    float* out = out_is_h ? g_h : out_ext;
    int tid = threadIdx.x;
    int base = blockIdx.x * NODES;

    // stage combined weights: rows 0..63 = Wn, rows 64..127 = Ws
    #pragma unroll
    for (int i = tid; i < 128 * OUT; i += 256)
        sW[i] = (i < 64 * OUT) ? Wn[i] : Ws[i - 64 * OUT];
    if (tid < OUT) sb[tid] = bias[tid];
    __syncthreads();

    int ln = tid >> 2;          // local node 0..63
    int q  = tid & 3;
    int n  = base + ln;
    int nc = (n < N_NODES) ? n : (N_NODES - 1);   // clamp for safe reads

    const float* ms = g_sum + (size_t)nc * 64;    // mean source (pre-division)
    const float* xs = feat  + (size_t)nc * 64;    // self features
    float inv = 1.0f / fmaxf(g_deg[nc], 1.0f);

    unsigned long long acc[JB * 2];
    #pragma unroll
    for (int i = 0; i < JB * 2; i++) acc[i] = 0ULL;   // {0.f, 0.f}

    const float* wq = sW + (q << 2);

    // k = 0..63 : mean * Wn
    #pragma unroll 8
    for (int k = 0; k < 64; k++) {
        float xm = ms[k] * inv;
        unsigned long long xm2;
        asm("mov.b64 %0, {%1,%1};" : "=l"(xm2) : "f"(xm));
        const float* wr = wq + k * OUT;
        #pragma unroll
        for (int j8 = 0; j8 < JB; j8++) {
            ulonglong2 w = *(const ulonglong2*)(wr + j8 * 16);
            FMA2(acc[j8 * 2],     xm2, w.x);
            FMA2(acc[j8 * 2 + 1], xm2, w.y);
        }
    }
    // k = 64..127 : feat * Ws
    #pragma unroll 8
    for (int k = 0; k < 64; k++) {
        float xm = xs[k];
        unsigned long long xm2;
        asm("mov.b64 %0, {%1,%1};" : "=l"(xm2) : "f"(xm));
        const float* wr = wq + (k + 64) * OUT;
        #pragma unroll
        for (int j8 = 0; j8 < JB; j8++) {
            ulonglong2 w = *(const ulonglong2*)(wr + j8 * 16);
            FMA2(acc[j8 * 2],     xm2, w.x);
            FMA2(acc[j8 * 2 + 1], xm2, w.y);
        }
    }

    // epilogue: unpack, +bias, relu, store float4 per j8 block
    if (n < N_NODES) {
        #pragma unroll
        for (int j8 = 0; j8 < JB; j8++) {
            int jb = j8 * 16 + (q << 2);
            float o[4];
            asm("mov.b64 {%0,%1}, %2;" : "=f"(o[0]), "=f"(o[1]) : "l"(acc[j8 * 2]));
            asm("mov.b64 {%0,%1}, %2;" : "=f"(o[2]), "=f"(o[3]) : "l"(acc[j8 * 2 + 1]));
            #pragma unroll
            for (int t = 0; t < 4; t++) {
                o[t] += sb[jb + t];
                if (relu) o[t] = fmaxf(o[t], 0.0f);
            }
            *(float4*)(out + (size_t)n * OUT + jb) = *(float4*)o;
        }
    }
}

// ---------------- launch ----------------
extern "C" void kernel_launch(void* const* d_in, const int* in_sizes, int n_in,
                              void* d_out, int out_size) {
    const float* x   = (const float*)d_in[0];
    const void*  ei  = d_in[1];
    const float* W1n = (const float*)d_in[2];
    const float* W1s = (const float*)d_in[3];
    const float* b1  = (const float*)d_in[4];
    const float* W2n = (const float*)d_in[5];
    const float* W2s = (const float*)d_in[6];
    const float* b2  = (const float*)d_in[7];
    float* out = (float*)d_out;

    // 0) detect edge_index element width
    detect_kernel<<<1, 1>>>((const int*)ei);

    // 1) zero accumulator + degree
    {
        int n4 = (N_NODES * 64) / 4 + N_NODES / 4;
        zero_sum_deg_kernel<<<(n4 + 255) / 256, 256>>>();
    }

    // 2) layer-1 scatter: sum x[src] into g_sum, count degree
    {
        long long total = (long long)N_EDGES * 16;
        int blocks = (int)((total + 255) / 256);
        scatter_kernel<<<blocks, 256>>>(x, ei, /*use_h=*/0, /*do_deg=*/1);
    }

    // 3) layer-1 transform: g_h = relu(mean@W1n + x@W1s + b1)
    {
        int blocks = (N_NODES + 63) / 64;
        sage_gemm2_kernel<64><<<blocks, 256>>>(x, W1n, W1s, b1, nullptr,
                                               /*feat_is_h=*/0, /*out_is_h=*/1, /*relu=*/1);
    }

    // 4) re-zero accumulator
    {
        int n4 = (N_NODES * 64) / 4;
        zero_sum_kernel<<<(n4 + 255) / 256, 256>>>();
    }

    // 5) layer-2 scatter: sum g_h[src] into g_sum
    {
        long long total = (long long)N_EDGES * 16;
        int blocks = (int)((total + 255) / 256);
        scatter_kernel<<<blocks, 256>>>(nullptr, ei, /*use_h=*/1, /*do_deg=*/0);
    }

    // 6) layer-2 transform: out = mean2@W2n + g_h@W2s + b2
    {
        int blocks = (N_NODES + 63) / 64;
        sage_gemm2_kernel<32><<<blocks, 256>>>(nullptr, W2n, W2s, b2, out,
                                               /*feat_is_h=*/1, /*out_is_h=*/0, /*relu=*/0);
    }
}